// round 1
// baseline (speedup 1.0000x reference)
#include <cuda_runtime.h>

#define NNODES 20000
#define NEDGES 640000
#define RREL 64
#define BBASIS 16
#define DIN 128
#define DOUT 128
#define KG (BBASIS * DIN)   /* 2048 */
#define KTOT (KG + DIN)     /* 2176 */

// Scratch (static device globals -- no allocation in kernel_launch)
__device__ float g_G[(size_t)NNODES * KG];   // [N][B][IN] accumulated inputs, 164 MB
__device__ int g_cnt[NNODES];
__device__ int g_cur[NNODES];
__device__ int g_off[NNODES + 1];
__device__ int g_perm[NEDGES];

// ---------------- counting sort by dst ----------------

__global__ void k_init(int n) {
    int i = blockIdx.x * blockDim.x + threadIdx.x;
    if (i < n) { g_cnt[i] = 0; g_cur[i] = 0; }
}

__global__ void k_hist(const int* __restrict__ dst, int e) {
    int i = blockIdx.x * blockDim.x + threadIdx.x;
    if (i < e) atomicAdd(&g_cnt[dst[i]], 1);
}

// single-block exclusive scan over N=20000 counts
__global__ void k_scan(int n) {
    __shared__ int sums[1024];
    int t = threadIdx.x;
    const int chunk = (n + 1023) / 1024;
    int base = t * chunk;
    int s = 0;
    for (int j = 0; j < chunk; j++) {
        int idx = base + j;
        if (idx < n) s += g_cnt[idx];
    }
    sums[t] = s;
    __syncthreads();
    for (int d = 1; d < 1024; d <<= 1) {
        int v = (t >= d) ? sums[t - d] : 0;
        __syncthreads();
        sums[t] += v;
        __syncthreads();
    }
    int run = (t == 0) ? 0 : sums[t - 1];
    for (int j = 0; j < chunk; j++) {
        int idx = base + j;
        if (idx < n) { g_off[idx] = run; run += g_cnt[idx]; }
    }
    if (t == 1023) g_off[n] = run;
}

__global__ void k_scatter(const int* __restrict__ dst, int e) {
    int i = blockIdx.x * blockDim.x + threadIdx.x;
    if (i < e) {
        int d = dst[i];
        int p = g_off[d] + atomicAdd(&g_cur[d], 1);
        g_perm[p] = i;
    }
}

// ---------------- edge accumulation: G[d,b,i] = sum_e norm_e * w_comp[r_e,b] * x[src_e,i] ----------------
// One block per destination node. 256 threads: thread owns (b = t>>4, i0 = (t&15)*8 .. +7).
// x (10 MB) is L2-resident; no atomics since edges are dst-sorted.

__global__ void __launch_bounds__(256) k_edge(
    const float* __restrict__ x, const float* __restrict__ wcomp,
    const float* __restrict__ norm, const int* __restrict__ src,
    const int* __restrict__ et)
{
    __shared__ float wc_s[RREL * BBASIS];
    int t = threadIdx.x;
    for (int j = t; j < RREL * BBASIS; j += 256) wc_s[j] = wcomp[j];
    __syncthreads();

    int d = blockIdx.x;
    int b = t >> 4;
    int i0 = (t & 15) << 3;

    float a0 = 0.f, a1 = 0.f, a2 = 0.f, a3 = 0.f;
    float a4 = 0.f, a5 = 0.f, a6 = 0.f, a7 = 0.f;

    int k0 = g_off[d], k1 = g_off[d + 1];

    int s = 0, r = 0; float nv = 0.f;
    if (k0 < k1) {
        int e = g_perm[k0];
        s = src[e]; r = et[e]; nv = norm[e];
    }
    for (int k = k0; k < k1; k++) {
        int cs = s, cr = r; float cn = nv;
        // prefetch next edge's scalars (hides the perm->src/et/norm chase)
        if (k + 1 < k1) {
            int e = g_perm[k + 1];
            s = src[e]; r = et[e]; nv = norm[e];
        }
        float cb = cn * wc_s[(cr << 4) + b];
        const float4* xr = (const float4*)(x + (size_t)cs * DIN + i0);
        float4 v0 = __ldg(xr);
        float4 v1 = __ldg(xr + 1);
        a0 += cb * v0.x; a1 += cb * v0.y; a2 += cb * v0.z; a3 += cb * v0.w;
        a4 += cb * v1.x; a5 += cb * v1.y; a6 += cb * v1.z; a7 += cb * v1.w;
    }

    float* gp = g_G + (size_t)d * KG + (b << 7) + i0;
    *(float4*)gp       = make_float4(a0, a1, a2, a3);
    *(float4*)(gp + 4) = make_float4(a4, a5, a6, a7);
}

// ---------------- fused GEMM: out = relu([G | x] @ [weight_flat ; loop_weight] + bias) ----------------
// M=20000, N=128, K=2176. BM=64, BN=128, BK=16, 256 threads, 8x4 per thread.

__global__ void __launch_bounds__(256) k_gemm(
    const float* __restrict__ x, const float* __restrict__ weight,
    const float* __restrict__ loopw, const float* __restrict__ bias,
    float* __restrict__ out, int M)
{
    __shared__ float As[16][68];    // transposed A tile, padded
    __shared__ float Bs[16][128];

    int t = threadIdx.x;
    int tc = t & 31, tr = t >> 5;
    int m0 = tr * 8, n0 = tc * 4;
    int blockM = blockIdx.x * 64;

    float acc[8][4];
#pragma unroll
    for (int i = 0; i < 8; i++)
#pragma unroll
        for (int j = 0; j < 4; j++) acc[i][j] = 0.f;

    // A-tile load mapping: one float4 per thread
    int ar = t >> 2;            // 0..63 (row within tile)
    int ac = (t & 3) << 2;      // 0,4,8,12 (k within tile)
    int arow = blockM + ar;
    // B-tile load mapping: two float4 per thread
    int br = t >> 4;            // 0..15 (k within tile)
    int bc = (t & 15) << 3;     // 0..120

    for (int k0 = 0; k0 < KTOT; k0 += 16) {
        // global loads into registers
        float4 av = make_float4(0.f, 0.f, 0.f, 0.f);
        int ka = k0 + ac;
        if (arow < M) {
            if (ka < KG) av = *(const float4*)(g_G + (size_t)arow * KG + ka);
            else         av = *(const float4*)(x + (size_t)arow * DIN + (ka - KG));
        }
        int brow = k0 + br;
        const float* Bsrc = (brow < KG) ? (weight + (size_t)brow * DOUT)
                                        : (loopw + (size_t)(brow - KG) * DOUT);
        float4 bv0 = *(const float4*)(Bsrc + bc);
        float4 bv1 = *(const float4*)(Bsrc + bc + 4);

        __syncthreads();   // previous tile fully consumed
        As[ac + 0][ar] = av.x;
        As[ac + 1][ar] = av.y;
        As[ac + 2][ar] = av.z;
        As[ac + 3][ar] = av.w;
        *(float4*)&Bs[br][bc]     = bv0;
        *(float4*)&Bs[br][bc + 4] = bv1;
        __syncthreads();

#pragma unroll
        for (int kk = 0; kk < 16; kk++) {
            float4 av0 = *(float4*)&As[kk][m0];
            float4 av1 = *(float4*)&As[kk][m0 + 4];
            float4 bb  = *(float4*)&Bs[kk][n0];
            float am[8] = {av0.x, av0.y, av0.z, av0.w, av1.x, av1.y, av1.z, av1.w};
            float bn[4] = {bb.x, bb.y, bb.z, bb.w};
#pragma unroll
            for (int i = 0; i < 8; i++)
#pragma unroll
                for (int j = 0; j < 4; j++)
                    acc[i][j] += am[i] * bn[j];
        }
    }

    float4 bz = *(const float4*)(bias + n0);
#pragma unroll
    for (int i = 0; i < 8; i++) {
        int m = blockM + m0 + i;
        if (m < M) {
            float4 o;
            o.x = fmaxf(acc[i][0] + bz.x, 0.f);
            o.y = fmaxf(acc[i][1] + bz.y, 0.f);
            o.z = fmaxf(acc[i][2] + bz.z, 0.f);
            o.w = fmaxf(acc[i][3] + bz.w, 0.f);
            *(float4*)(out + (size_t)m * DOUT + n0) = o;
        }
    }
}

// ---------------- launch ----------------

extern "C" void kernel_launch(void* const* d_in, const int* in_sizes, int n_in,
                              void* d_out, int out_size) {
    const float* x      = (const float*)d_in[0];
    const float* weight = (const float*)d_in[1];
    const float* wcomp  = (const float*)d_in[2];
    const float* bias   = (const float*)d_in[3];
    const float* loopw  = (const float*)d_in[4];
    const float* norm   = (const float*)d_in[5];
    const int*   src    = (const int*)d_in[6];
    const int*   dst    = (const int*)d_in[7];
    const int*   et     = (const int*)d_in[8];
    float* out = (float*)d_out;

    int N = in_sizes[0] / DIN;
    int E = in_sizes[6];

    k_init<<<(N + 255) / 256, 256>>>(N);
    k_hist<<<(E + 255) / 256, 256>>>(dst, E);
    k_scan<<<1, 1024>>>(N);
    k_scatter<<<(E + 255) / 256, 256>>>(dst, E);
    k_edge<<<N, 256>>>(x, wcomp, norm, src, et);
    k_gemm<<<(N + 63) / 64, 256>>>(x, weight, loopw, bias, out, N);
}